// round 15
// baseline (speedup 1.0000x reference)
#include <cuda_runtime.h>
#include <cuda_fp16.h>
#include <cstdint>

// ArcFace loss, fused. FP16 HMMA (m16n8k16.f16), warp tile 64x64, fp16 acc.
// This round: W normalization folded into k2 via per-ntile claim flags
// (first CTA of each pair normalizes the 128-row W slice; partner spins
// briefly). The separate k1b DRAM pass and its launch disappear.
// B=512, D=512, C=64000.
constexpr int BB = 512;
constexpr int DD = 512;
constexpr int CC = 64000;

constexpr int BM = 256, BN = 128, BK = 32;
constexpr int MT = BB / BM;    // 2
constexpr int NT = CC / BN;    // 500
constexpr int NSTG = DD / BK;  // 16
constexpr int AROW = 40;       // smem row stride (halfs); ldsm conflict-free
constexpr int A_STG = BM * AROW * 2;   // 20480 B
constexpr int B_STG = BN * AROW * 2;   // 10240 B
constexpr int NPIPE = 3;

// dynamic smem layout
constexpr int A_OFF  = 0;                       // 3 stages
constexpr int B_OFF  = NPIPE * A_STG;           // 61440, 3 stages
constexpr int SY_OFF = B_OFF + NPIPE * B_STG;   // 92160: 256 ints
constexpr int RA_OFF = SY_OFF + 1024;           // 93184: 256x2 floats
constexpr int SMEM_TOTAL = RA_OFF + 2048;       // 95232 (x2 CTA = 190KB <= 228KB)

__device__ __half g_xnh[BB * DD];   // normalized x fp16 (GEMM A)
__device__ __half g_wnh[CC * DD];   // normalized W fp16 (filled inside k2)
__device__ int    g_y[BB];
__device__ double g_num[BB];        // per-row numerator (from k1)
__device__ double g_excl[BB];       // per-row exclusive exp-sum (k2 atomics)
__device__ int    g_wflag[NT];      // 0=todo, 1=claimed, 2=ready

// ---------------- PTX helpers ----------------
__device__ __forceinline__ void ldsm4(uint32_t* r, uint32_t a) {
    asm volatile("ldmatrix.sync.aligned.m8n8.x4.shared.b16 {%0,%1,%2,%3}, [%4];"
        : "=r"(r[0]), "=r"(r[1]), "=r"(r[2]), "=r"(r[3]) : "r"(a));
}
__device__ __forceinline__ void mma16816h(uint32_t* c, const uint32_t* a, uint32_t b0, uint32_t b1) {
    asm volatile("mma.sync.aligned.m16n8k16.row.col.f16.f16.f16.f16 "
        "{%0,%1}, {%2,%3,%4,%5}, {%6,%7}, {%0,%1};"
        : "+r"(c[0]), "+r"(c[1])
        : "r"(a[0]), "r"(a[1]), "r"(a[2]), "r"(a[3]), "r"(b0), "r"(b1));
}
__device__ __forceinline__ void cpasync16(uint32_t smem, const void* gptr) {
    asm volatile("cp.async.cg.shared.global [%0], [%1], 16;"
        :: "r"(smem), "l"(gptr) : "memory");
}
__device__ __forceinline__ void cpcommit() { asm volatile("cp.async.commit_group;" ::: "memory"); }
__device__ __forceinline__ void cpwait1() { asm volatile("cp.async.wait_group 1;" ::: "memory"); }

// ---------------------------------------------------------------------------
// k0: decode labels (int64 vs int32 layout sniff) + zero flags/accumulators.
// ---------------------------------------------------------------------------
__global__ void k0_init(const int* __restrict__ yw) {
    __shared__ int oddnz;
    int t = threadIdx.x; // 512
    if (t == 0) oddnz = 0;
    __syncthreads();
    if (t < 256 && yw[2 * t + 1] != 0) atomicOr(&oddnz, 1);
    __syncthreads();
    g_y[t] = oddnz ? yw[t] : (int)((const long long*)yw)[t];
    g_excl[t] = 0.0;
    if (t < NT) g_wflag[t] = 0;
}

// ---------------------------------------------------------------------------
// k1: per-row: L2-normalize x -> fp16 AND exact numerator
// num = 64*cos(acos(clip(x̂·W_y/|W_y|)) + 0.5). 512 blocks x 128 threads.
// ---------------------------------------------------------------------------
__global__ void k1_norm_x(const float* __restrict__ x, const float* __restrict__ Wm) {
    int row = blockIdx.x;
    int t = threadIdx.x; // 128
    int yb = g_y[row];
    float4 v  = ((const float4*)(x + row * DD))[t];
    float4 wv = ((const float4*)(Wm + (size_t)yb * DD))[t];
    float ss  = v.x * v.x + v.y * v.y + v.z * v.z + v.w * v.w;
    float dr  = wv.x * v.x + wv.y * v.y + wv.z * v.z + wv.w * v.w;
    float wss = wv.x * wv.x + wv.y * wv.y + wv.z * wv.z + wv.w * wv.w;
    #pragma unroll
    for (int o = 16; o; o >>= 1) {
        ss  += __shfl_xor_sync(0xffffffffu, ss, o);
        dr  += __shfl_xor_sync(0xffffffffu, dr, o);
        wss += __shfl_xor_sync(0xffffffffu, wss, o);
    }
    __shared__ float ws[4], wd[4], ww[4];
    if ((t & 31) == 0) { ws[t >> 5] = ss; wd[t >> 5] = dr; ww[t >> 5] = wss; }
    __syncthreads();
    float tot = ws[0] + ws[1] + ws[2] + ws[3];
    float sc = 1.0f / fmaxf(sqrtf(tot), 1e-12f);
    __half2 p0 = __floats2half2_rn(v.x * sc, v.y * sc);
    __half2 p1 = __floats2half2_rn(v.z * sc, v.w * sc);
    ((__half2*)(g_xnh + row * DD))[2 * t]     = p0;
    ((__half2*)(g_xnh + row * DD))[2 * t + 1] = p1;

    if (t == 0) {
        float dsum = wd[0] + wd[1] + wd[2] + wd[3];
        float wsum = ww[0] + ww[1] + ww[2] + ww[3];
        double tgt = (double)(dsum * sc) / fmax(sqrt((double)wsum), 1e-12);
        double tc = fmin(fmax(tgt, -1.0 + 1e-7), 1.0 - 1e-7);
        g_num[row] = 64.0 * cos(acos(tc) + 0.5);
    }
}

// ---------------------------------------------------------------------------
// k2: fp16 HMMA GEMM + on-demand W normalization.
// 256 threads / 8 warps (4x2, warp tile 64x64), 256Mx128N, BK=32, 3-stage
// cp.async, 2 CTAs/SM. First CTA of each nt-pair claims the W slice and
// normalizes it (one warp per row, 16 rows/warp — same math/order as the old
// k1b, so g_wnh is bit-identical); partner spins until ready.
// ---------------------------------------------------------------------------
__global__ __launch_bounds__(256, 2) void k2_gemm(const float* __restrict__ Wm) {
    extern __shared__ char smem[];
    const uint32_t sb = (uint32_t)__cvta_generic_to_shared(smem);
    const int t = threadIdx.x, lane = t & 31, wp = t >> 5;
    const int wm = wp >> 1, wn = wp & 1;       // 4x2 warps, tile 64x64
    const int mt = blockIdx.x, nt = blockIdx.y;
    const int m0 = mt * BM, n0 = nt * BN;

    if (t < BM) ((int*)(smem + SY_OFF))[t] = g_y[m0 + t];

    // ---- claim-or-wait: ensure g_wnh rows [n0, n0+BN) are normalized
    __shared__ int role;
    if (t == 0) role = (atomicCAS(&g_wflag[nt], 0, 1) == 0) ? 1 : 0;
    __syncthreads();
    if (role) {
        // one warp per row, 16 rows per warp (8 warps x 16 = 128 rows)
        for (int r = wp; r < BN; r += 8) {
            const float4* wr = (const float4*)(Wm + (size_t)(n0 + r) * DD);
            float4 v[4];
            float ss = 0.f;
            #pragma unroll
            for (int i = 0; i < 4; i++) {
                v[i] = wr[lane + i * 32];
                ss += v[i].x * v[i].x + v[i].y * v[i].y + v[i].z * v[i].z + v[i].w * v[i].w;
            }
            #pragma unroll
            for (int o = 16; o; o >>= 1) ss += __shfl_xor_sync(0xffffffffu, ss, o);
            float sc = 1.0f / fmaxf(sqrtf(ss), 1e-12f);
            __half2* out = (__half2*)(g_wnh + (size_t)(n0 + r) * DD);
            #pragma unroll
            for (int i = 0; i < 4; i++) {
                __half2 p0 = __floats2half2_rn(v[i].x * sc, v[i].y * sc);
                __half2 p1 = __floats2half2_rn(v[i].z * sc, v[i].w * sc);
                out[(lane + i * 32) * 2]     = p0;
                out[(lane + i * 32) * 2 + 1] = p1;
            }
        }
        __threadfence();
        __syncthreads();
        if (t == 0) atomicExch(&g_wflag[nt], 2);
    } else {
        if (t == 0) {
            while (atomicAdd(&g_wflag[nt], 0) != 2) __nanosleep(64);
            __threadfence();
        }
        __syncthreads();
    }

    // producers: A 4 rows/thread (stride 64), B 2 rows/thread (stride 64)
    const int pr = t >> 2, pc = (t & 3) * 8;
    const __half* gA = g_xnh + (m0 + pr) * DD + pc;
    const __half* gB = g_wnh + (size_t)(n0 + pr) * DD + pc;
    const uint32_t sA = sb + A_OFF + (pr * AROW + pc) * 2;
    const uint32_t sB = sb + B_OFF + (pr * AROW + pc) * 2;
    constexpr uint32_t ARS = 64 * AROW * 2;   // 64-row stride in smem bytes
    uint32_t woA = 0, woB = 0;

    auto fill = [&]() {
        cpasync16(sA + woA,           gA);
        cpasync16(sA + woA + ARS,     gA + 64 * DD);
        cpasync16(sA + woA + 2 * ARS, gA + 128 * DD);
        cpasync16(sA + woA + 3 * ARS, gA + 192 * DD);
        cpasync16(sB + woB,           gB);
        cpasync16(sB + woB + ARS,     gB + 64 * DD);
        gA += BK; gB += BK;
        woA += A_STG; if (woA == NPIPE * A_STG) woA = 0;
        woB += B_STG; if (woB == NPIPE * B_STG) woB = 0;
    };

    uint32_t acc[4][8][2];   // fp16x2 accumulators, 64 regs
    #pragma unroll
    for (int i = 0; i < 4; i++)
        #pragma unroll
        for (int j = 0; j < 8; j++) { acc[i][j][0] = 0u; acc[i][j][1] = 0u; }

    uint32_t aoff[4], boff[4];
    #pragma unroll
    for (int mf = 0; mf < 4; mf++)
        aoff[mf] = sb + A_OFF + ((wm * 64 + mf * 16 + (lane & 15)) * AROW + (lane >> 4) * 8) * 2;
    #pragma unroll
    for (int g = 0; g < 4; g++)
        boff[g] = sb + B_OFF + ((wn * 64 + g * 16 + (lane & 15)) * AROW + (lane >> 4) * 8) * 2;

    fill(); cpcommit();
    fill(); cpcommit();

    uint32_t roA = 0, roB = 0;
    for (int ks = 0; ks < NSTG; ks++) {
        cpwait1();
        __syncthreads();
        if (ks + 2 < NSTG) fill();
        cpcommit();

        #pragma unroll
        for (int kc = 0; kc < 2; kc++) {
            uint32_t bfrag[4][4];
            #pragma unroll
            for (int g = 0; g < 4; g++)
                ldsm4(bfrag[g], boff[g] + roB + kc * 32);
            #pragma unroll
            for (int mf = 0; mf < 4; mf++) {
                uint32_t afrag[4];
                ldsm4(afrag, aoff[mf] + roA + kc * 32);
                #pragma unroll
                for (int nf = 0; nf < 8; nf++) {
                    int g = nf >> 1, h = nf & 1;
                    mma16816h(acc[mf][nf], afrag, bfrag[g][h], bfrag[g][2 + h]);
                }
            }
        }
        roA += A_STG; if (roA == NPIPE * A_STG) roA = 0;
        roB += B_STG; if (roB == NPIPE * B_STG) roB = 0;
    }
    __syncthreads();

    // epilogue: theta = acc; exp + mask + row-sum; RED into g_excl
    const int* sy = (const int*)(smem + SY_OFF);
    float* rowacc = (float*)(smem + RA_OFF);
    #pragma unroll
    for (int mf = 0; mf < 4; mf++) {
        #pragma unroll
        for (int h = 0; h < 2; h++) {
            int row = wm * 64 + mf * 16 + h * 8 + (lane >> 2);
            int yrel = sy[row] - n0;
            float rsum = 0.f;
            #pragma unroll
            for (int nf = 0; nf < 8; nf++) {
                int nl = wn * 64 + nf * 8 + (lane & 3) * 2;
                float2 th = __half22float2(*(const __half2*)&acc[mf][nf][h]);
                float e0 = __expf(64.0f * th.x);
                float e1 = __expf(64.0f * th.y);
                rsum += (nl     == yrel) ? 0.f : e0;
                rsum += (nl + 1 == yrel) ? 0.f : e1;
            }
            rsum += __shfl_xor_sync(0xffffffffu, rsum, 1);
            rsum += __shfl_xor_sync(0xffffffffu, rsum, 2);
            if ((lane & 3) == 0) rowacc[row * 2 + wn] = rsum;
        }
    }
    __syncthreads();
    if (t < BM)
        atomicAdd(&g_excl[m0 + t], (double)(rowacc[t * 2] + rowacc[t * 2 + 1]));
}

// ---------------------------------------------------------------------------
// k3: final. One block, 512 threads: term = num - log(exp(num)+excl);
// deterministic tree mean.
// ---------------------------------------------------------------------------
__global__ __launch_bounds__(512) void k3_final(float* __restrict__ out) {
    __shared__ double sd[512];
    int t = threadIdx.x;
    double num = g_num[t];
    sd[t] = num - log(exp(num) + g_excl[t]);
    __syncthreads();
    for (int s = 256; s; s >>= 1) {
        if (t < s) sd[t] += sd[t + s];
        __syncthreads();
    }
    if (t == 0) out[0] = (float)(-sd[0] / (double)BB);
}

extern "C" void kernel_launch(void* const* d_in, const int* in_sizes, int n_in,
                              void* d_out, int out_size) {
    const float* x = (const float*)d_in[0];
    const int*   y = (const int*)d_in[1];
    const float* W = (const float*)d_in[2];

    cudaFuncSetAttribute(k2_gemm, cudaFuncAttributeMaxDynamicSharedMemorySize, SMEM_TOTAL);

    k0_init<<<1, BB>>>(y);
    k1_norm_x<<<BB, 128>>>(x, W);
    k2_gemm<<<dim3(MT, NT), 256, SMEM_TOTAL>>>(W);
    k3_final<<<1, BB>>>((float*)d_out);
}

// round 16
// speedup vs baseline: 1.1811x; 1.1811x over previous
#include <cuda_runtime.h>
#include <cuda_fp16.h>
#include <cstdint>

// ArcFace loss, fused. FP16 HMMA (m16n8k16.f16), fp16 accumulate.
// This round: k2 at 3 CTAs/SM (BM=128, warp 64x32, regs<=85, smem 64KB,
// NPIPE=3) for 6 warps/SMSP of latency hiding. Small kernels = round-13 best.
// B=512, D=512, C=64000.
constexpr int BB = 512;
constexpr int DD = 512;
constexpr int CC = 64000;

constexpr int BM = 128, BN = 128, BK = 32;
constexpr int MT = BB / BM;    // 4
constexpr int NT = CC / BN;    // 500
constexpr int NSTG = DD / BK;  // 16
constexpr int AROW = 40;       // smem row stride (halfs); ldsm conflict-free
constexpr int STG = BM * AROW * 2;   // 10240 B (A and B equal)
constexpr int NPIPE = 3;

// dynamic smem layout (per CTA, 3 CTAs/SM)
constexpr int A_OFF  = 0;                    // 3 stages
constexpr int B_OFF  = NPIPE * STG;          // 30720, 3 stages
constexpr int SY_OFF = B_OFF + NPIPE * STG;  // 61440: 128 ints
constexpr int RA_OFF = SY_OFF + 512;         // 61952: 128x4 floats
constexpr int SMEM_TOTAL = RA_OFF + 2048;    // 64000 (x3 CTA = 192KB <= 228KB)

__device__ float  g_xn[BB * DD];    // normalized x fp32 (k3 exact dot)
__device__ __half g_xnh[BB * DD];   // normalized x fp16 (GEMM A)
__device__ __half g_wnh[CC * DD];   // normalized W fp16 (GEMM B)
__device__ int    g_y[BB];
__device__ float  g_partial[BB * NT];  // [row][ntile] — k3-coalesced
__device__ double g_term[BB];
__device__ unsigned int g_k3done;   // zero-init; reset by finishing block

// ---------------- PTX helpers ----------------
__device__ __forceinline__ void ldsm4(uint32_t* r, uint32_t a) {
    asm volatile("ldmatrix.sync.aligned.m8n8.x4.shared.b16 {%0,%1,%2,%3}, [%4];"
        : "=r"(r[0]), "=r"(r[1]), "=r"(r[2]), "=r"(r[3]) : "r"(a));
}
__device__ __forceinline__ void mma16816h(uint32_t* c, const uint32_t* a, uint32_t b0, uint32_t b1) {
    asm volatile("mma.sync.aligned.m16n8k16.row.col.f16.f16.f16.f16 "
        "{%0,%1}, {%2,%3,%4,%5}, {%6,%7}, {%0,%1};"
        : "+r"(c[0]), "+r"(c[1])
        : "r"(a[0]), "r"(a[1]), "r"(a[2]), "r"(a[3]), "r"(b0), "r"(b1));
}
__device__ __forceinline__ void cpasync16(uint32_t smem, const void* gptr) {
    asm volatile("cp.async.cg.shared.global [%0], [%1], 16;"
        :: "r"(smem), "l"(gptr) : "memory");
}
__device__ __forceinline__ void cpcommit() { asm volatile("cp.async.commit_group;" ::: "memory"); }
__device__ __forceinline__ void cpwait1() { asm volatile("cp.async.wait_group 1;" ::: "memory"); }

// ---------------------------------------------------------------------------
// k1: L2-normalize rows of x -> fp32 + fp16; block 0 also decodes labels
// (int64 vs int32 layout sniff: labels < 64000 -> int64 high words all zero).
// ---------------------------------------------------------------------------
__global__ void k1_norm_x(const float* __restrict__ x, const int* __restrict__ yw) {
    int row = blockIdx.x;
    int t = threadIdx.x; // 128
    float4 v = ((const float4*)(x + row * DD))[t];
    float ss = v.x * v.x + v.y * v.y + v.z * v.z + v.w * v.w;
    #pragma unroll
    for (int o = 16; o; o >>= 1) ss += __shfl_xor_sync(0xffffffffu, ss, o);
    __shared__ float ws[4];
    if ((t & 31) == 0) ws[t >> 5] = ss;
    __syncthreads();
    float tot = ws[0] + ws[1] + ws[2] + ws[3];
    float sc = 1.0f / fmaxf(sqrtf(tot), 1e-12f);
    float4 o4 = make_float4(v.x * sc, v.y * sc, v.z * sc, v.w * sc);
    ((float4*)(g_xn + row * DD))[t] = o4;
    __half2 p0 = __floats2half2_rn(o4.x, o4.y);
    __half2 p1 = __floats2half2_rn(o4.z, o4.w);
    ((__half2*)(g_xnh + row * DD))[2 * t]     = p0;
    ((__half2*)(g_xnh + row * DD))[2 * t + 1] = p1;

    if (row == 0) {
        __shared__ int oddnz;
        if (t == 0) oddnz = 0;
        __syncthreads();
        int nz = 0;
        for (int i = t; i < 256; i += 128)
            if (yw[2 * i + 1] != 0) nz = 1;
        if (nz) atomicOr(&oddnz, 1);
        __syncthreads();
        for (int i = t; i < BB; i += 128)
            g_y[i] = oddnz ? yw[i] : (int)((const long long*)yw)[i];
    }
}

// k1b: L2-normalize rows of W -> fp16. One warp per row, 8 rows per block.
__global__ __launch_bounds__(256) void k1b_norm_w(const float* __restrict__ Wm) {
    int wid = threadIdx.x >> 5, lane = threadIdx.x & 31;
    int row = blockIdx.x * 8 + wid;
    const float4* wr = (const float4*)(Wm + (size_t)row * DD);
    float4 v[4];
    float ss = 0.f;
    #pragma unroll
    for (int i = 0; i < 4; i++) {
        v[i] = wr[lane + i * 32];
        ss += v[i].x * v[i].x + v[i].y * v[i].y + v[i].z * v[i].z + v[i].w * v[i].w;
    }
    #pragma unroll
    for (int o = 16; o; o >>= 1) ss += __shfl_xor_sync(0xffffffffu, ss, o);
    float sc = 1.0f / fmaxf(sqrtf(ss), 1e-12f);
    __half2* out = (__half2*)(g_wnh + (size_t)row * DD);
    #pragma unroll
    for (int i = 0; i < 4; i++) {
        __half2 p0 = __floats2half2_rn(v[i].x * sc, v[i].y * sc);
        __half2 p1 = __floats2half2_rn(v[i].z * sc, v[i].w * sc);
        out[(lane + i * 32) * 2]     = p0;
        out[(lane + i * 32) * 2 + 1] = p1;
    }
}

// ---------------------------------------------------------------------------
// k2: fp16 HMMA GEMM, 256 threads / 8 warps (2x4, warp tile 64x32), 128Mx128N,
// BK=32, 3-stage cp.async (single sync/stage), 3 CTAs/SM, fp16 accumulators.
// ---------------------------------------------------------------------------
__global__ __launch_bounds__(256, 3) void k2_gemm() {
    extern __shared__ char smem[];
    const uint32_t sb = (uint32_t)__cvta_generic_to_shared(smem);
    const int t = threadIdx.x, lane = t & 31, wp = t >> 5;
    const int wm = wp >> 2, wn = wp & 3;       // 2x4 warps, warp tile 64x32
    const int mt = blockIdx.x, nt = blockIdx.y;
    const int m0 = mt * BM, n0 = nt * BN;

    if (t < BM) ((int*)(smem + SY_OFF))[t] = g_y[m0 + t];

    // producers: rows t>>2 and 64+(t>>2), col chunk (t&3)*8 halfs
    const int pr = t >> 2, pc = (t & 3) * 8;
    const __half* gA = g_xnh + (m0 + pr) * DD + pc;
    const __half* gB = g_wnh + (size_t)(n0 + pr) * DD + pc;
    const uint32_t sA = sb + A_OFF + (pr * AROW + pc) * 2;
    const uint32_t sB = sb + B_OFF + (pr * AROW + pc) * 2;
    constexpr uint32_t ARS = 64 * AROW * 2;
    uint32_t wo = 0;

    auto fill = [&]() {
        cpasync16(sA + wo,       gA);
        cpasync16(sA + wo + ARS, gA + 64 * DD);
        cpasync16(sB + wo,       gB);
        cpasync16(sB + wo + ARS, gB + 64 * DD);
        gA += BK; gB += BK;
        wo += STG; if (wo == NPIPE * STG) wo = 0;
    };

    uint32_t acc[4][4][2];   // fp16x2 accumulators, 32 regs
    #pragma unroll
    for (int i = 0; i < 4; i++)
        #pragma unroll
        for (int j = 0; j < 4; j++) { acc[i][j][0] = 0u; acc[i][j][1] = 0u; }

    uint32_t aoff[4], boff[2];
    #pragma unroll
    for (int mf = 0; mf < 4; mf++)
        aoff[mf] = sb + A_OFF + ((wm * 64 + mf * 16 + (lane & 15)) * AROW + (lane >> 4) * 8) * 2;
    #pragma unroll
    for (int g = 0; g < 2; g++)
        boff[g] = sb + B_OFF + ((wn * 32 + g * 16 + (lane & 15)) * AROW + (lane >> 4) * 8) * 2;

    fill(); cpcommit();
    fill(); cpcommit();

    uint32_t ro = 0;
    for (int ks = 0; ks < NSTG; ks++) {
        cpwait1();
        __syncthreads();
        if (ks + 2 < NSTG) fill();
        cpcommit();

        #pragma unroll
        for (int kc = 0; kc < 2; kc++) {
            uint32_t bfrag[2][4];
            ldsm4(bfrag[0], boff[0] + ro + kc * 32);
            ldsm4(bfrag[1], boff[1] + ro + kc * 32);
            #pragma unroll
            for (int mf = 0; mf < 4; mf++) {
                uint32_t afrag[4];
                ldsm4(afrag, aoff[mf] + ro + kc * 32);
                #pragma unroll
                for (int nf = 0; nf < 4; nf++) {
                    int g = nf >> 1, h = nf & 1;
                    mma16816h(acc[mf][nf], afrag, bfrag[g][h], bfrag[g][2 + h]);
                }
            }
        }
        ro += STG; if (ro == NPIPE * STG) ro = 0;
    }
    __syncthreads();

    // epilogue: theta = acc; exp + mask + row-sum; transposed partial store
    const int* sy = (const int*)(smem + SY_OFF);
    float* rowacc = (float*)(smem + RA_OFF);
    #pragma unroll
    for (int mf = 0; mf < 4; mf++) {
        #pragma unroll
        for (int h = 0; h < 2; h++) {
            int row = wm * 64 + mf * 16 + h * 8 + (lane >> 2);
            int yrel = sy[row] - n0;
            float rsum = 0.f;
            #pragma unroll
            for (int nf = 0; nf < 4; nf++) {
                int nl = wn * 32 + nf * 8 + (lane & 3) * 2;
                float2 th = __half22float2(*(const __half2*)&acc[mf][nf][h]);
                float e0 = __expf(64.0f * th.x);
                float e1 = __expf(64.0f * th.y);
                rsum += (nl     == yrel) ? 0.f : e0;
                rsum += (nl + 1 == yrel) ? 0.f : e1;
            }
            rsum += __shfl_xor_sync(0xffffffffu, rsum, 1);
            rsum += __shfl_xor_sync(0xffffffffu, rsum, 2);
            if ((lane & 3) == 0) rowacc[row * 4 + wn] = rsum;
        }
    }
    __syncthreads();
    if (t < BM)
        g_partial[(size_t)(m0 + t) * NT + nt] =
            (rowacc[t * 4] + rowacc[t * 4 + 1]) + (rowacc[t * 4 + 2] + rowacc[t * 4 + 3]);
}

// ---------------------------------------------------------------------------
// k3: per-row finalize (exact fp32 target logit) + fused final mean.
// 512 blocks x 512 threads; coalesced g_partial reads; last block performs
// the fixed-order deterministic reduction and resets the counter.
// ---------------------------------------------------------------------------
__global__ __launch_bounds__(512) void k3_final(const float* __restrict__ Wm,
                                                float* __restrict__ out) {
    __shared__ double sd[512];
    __shared__ float  sf[128], sg[128];
    __shared__ unsigned int rank;
    int b = blockIdx.x, t = threadIdx.x;
    int yb = g_y[b];

    double ex = (t < NT) ? (double)g_partial[(size_t)b * NT + t] : 0.0;

    if (t < 128) {
        float4 wv = ((const float4*)(Wm + (size_t)yb * DD))[t];
        float4 xv = ((const float4*)(g_xn + b * DD))[t];
        sf[t] = wv.x * xv.x + wv.y * xv.y + wv.z * xv.z + wv.w * xv.w;
        sg[t] = wv.x * wv.x + wv.y * wv.y + wv.z * wv.z + wv.w * wv.w;
    }
    sd[t] = ex;
    __syncthreads();
    for (int s = 256; s >= 128; s >>= 1) {
        if (t < s) sd[t] += sd[t + s];
        __syncthreads();
    }
    for (int s = 64; s; s >>= 1) {
        if (t < s) { sd[t] += sd[t + s]; sf[t] += sf[t + s]; sg[t] += sg[t + s]; }
        __syncthreads();
    }
    if (t == 0) {
        double tgt = (double)sf[0] / fmax(sqrt((double)sg[0]), 1e-12);
        double tc = fmin(fmax(tgt, -1.0 + 1e-7), 1.0 - 1e-7);
        double num = 64.0 * cos(acos(tc) + 0.5);
        double den = exp(num) + sd[0];
        g_term[b] = num - log(den);
        __threadfence();
        rank = atomicInc(&g_k3done, 0xffffffffu);
    }
    __syncthreads();

    if (rank == BB - 1) {            // last block: deterministic final reduce
        __threadfence();
        sd[t] = g_term[t];
        __syncthreads();
        for (int s = 256; s; s >>= 1) {
            if (t < s) sd[t] += sd[t + s];
            __syncthreads();
        }
        if (t == 0) {
            out[0] = (float)(-sd[0] / (double)BB);
            g_k3done = 0;            // reset for next (graph-replayed) call
        }
    }
}

extern "C" void kernel_launch(void* const* d_in, const int* in_sizes, int n_in,
                              void* d_out, int out_size) {
    const float* x = (const float*)d_in[0];
    const int*   y = (const int*)d_in[1];
    const float* W = (const float*)d_in[2];

    cudaFuncSetAttribute(k2_gemm, cudaFuncAttributeMaxDynamicSharedMemorySize, SMEM_TOTAL);

    k1_norm_x<<<BB, 128>>>(x, y);
    k1b_norm_w<<<CC / 8, 256>>>(W);
    k2_gemm<<<dim3(MT, NT), 256, SMEM_TOTAL>>>();
    k3_final<<<BB, 512>>>(W, (float*)d_out);
}